// round 15
// baseline (speedup 1.0000x reference)
#include <cuda_runtime.h>
#include <cuda_fp16.h>

#define BB 32
#define JJ 2048
#define II 16
#define NN 64
#define DD 32
#define SQ_EPS 1e-7f

// packed 2-wide fp32 FMA (sm_103a; only reachable via PTX)
#define FMA_F32X2(d, a, b, c) \
    asm("fma.rn.f32x2 %0, %1, %2, %3;" : "=l"(d) : "l"(a), "l"(b), "l"(c))
#define UNPACK_F32X2(lo, hi, in) \
    asm("mov.b64 {%0, %1}, %2;" : "=f"(lo), "=f"(hi) : "l"(in))

#define CP_ASYNC16(dst_u32, src_ptr) \
    asm volatile("cp.async.cg.shared.global [%0], [%1], 16;\n" \
                 :: "r"(dst_u32), "l"(src_ptr))

// ---------------- device scratch (no allocations allowed) ----------------
__device__ __half g_uhat[(size_t)BB * JJ * NN * DD];   // [b][j][n][d], 268 MB
__device__ float  g_v[BB * NN * DD];                   // [b][n][d]
__device__ float  g_blog[(size_t)BB * JJ * NN];        // [b][j][n], 16 MB
__device__ float  g_sp[64 * BB * NN * DD];             // partial s slices, 16 MB

// ---------------- K1: u_hat = einsum('bji,njdi') + partial sum_j u_hat ----------------
// (R13-exact: lane owns (n, dpair) -> half2 STG; dpair-major W pad-36; cp.async x2 buf)
#define K1_W_FLOATS (2 * 4 * 16 * 36)                 // 4608
#define K1_BUF_FLOATS (K1_W_FLOATS + 32 * 64)         // + xs 2048 = 6656
#define K1_SMEM (2 * K1_BUF_FLOATS * 4)               // 53248 B

__global__ __launch_bounds__(256) void k1_uhat(const float* __restrict__ x,
                                               const float* __restrict__ W) {
    extern __shared__ float sm1[];

    int np = blockIdx.x >> 5;        // n-pair
    int jc = blockIdx.x & 31;        // j-chunk (64 j)
    int t  = threadIdx.x;
    int w  = t >> 5;
    int lane = t & 31;
    int dp = lane & 15;              // d pair: d = 2dp, 2dp+1
    int nl = lane >> 4;              // n local (0/1)
    int bg = w & 3;                  // b-group: b in [8bg, 8bg+8)
    int js = w >> 2;                 // j-slot: jl in {2js, 2js+1}
    int n  = np * 2 + nl;

    unsigned sbase = (unsigned)__cvta_generic_to_shared(sm1);
    const float4* W4 = (const float4*)W;
    const float4* X4 = (const float4*)x;

    float2 sacc[8];
    #pragma unroll
    for (int bb = 0; bb < 8; bb++) sacc[bb] = make_float2(0.f, 0.f);

    auto stage = [&](int sub, int buf) {
        int j0 = jc * 64 + sub * 4;
        unsigned wb = sbase + buf * (K1_BUF_FLOATS * 4);
        unsigned xb = wb + K1_W_FLOATS * 4;
        #pragma unroll
        for (int r = 0; r < 4; r++) {
            int idx = r * 256 + t;
            int n_l = idx >> 9, rem = idx & 511;
            int jl = rem >> 7, d = (rem >> 2) & 31, q = rem & 3;
            const float4* src = &W4[(((np * 2 + n_l) * JJ + (j0 + jl)) << 7) + d * 4 + q];
            unsigned off = ((n_l * 4 + jl) * 16 + (d >> 1)) * 36 + (d & 1) * 16 + q * 4;
            CP_ASYNC16(wb + off * 4, src);
        }
        #pragma unroll
        for (int r = 0; r < 2; r++) {
            int idx = r * 256 + t;
            int b = idx >> 4, rr = idx & 15;
            const float4* src = &X4[(b * JJ + j0) * 4 + rr];
            CP_ASYNC16(xb + (b * 64 + rr * 4) * 4, src);
        }
        asm volatile("cp.async.commit_group;\n" ::: "memory");
    };

    stage(0, 0);
    int buf = 0;

    for (int sub = 0; sub < 16; sub++) {
        if (sub + 1 < 16) {
            stage(sub + 1, buf ^ 1);
            asm volatile("cp.async.wait_group 1;\n" ::: "memory");
        } else {
            asm volatile("cp.async.wait_group 0;\n" ::: "memory");
        }
        __syncthreads();

        const float* Ws = sm1 + buf * K1_BUF_FLOATS;
        const float* xs = Ws + K1_W_FLOATS;
        int j0 = jc * 64 + sub * 4;

        #pragma unroll
        for (int jj = 0; jj < 2; jj++) {
            int jl = js * 2 + jj;
            int jglob = j0 + jl;
            const float* row = &Ws[((nl * 4 + jl) * 16 + dp) * 36];
            ulonglong2 wa0 = *(const ulonglong2*)(row);
            ulonglong2 wa1 = *(const ulonglong2*)(row + 4);
            ulonglong2 wa2 = *(const ulonglong2*)(row + 8);
            ulonglong2 wa3 = *(const ulonglong2*)(row + 12);
            ulonglong2 wb0 = *(const ulonglong2*)(row + 16);
            ulonglong2 wb1 = *(const ulonglong2*)(row + 20);
            ulonglong2 wb2 = *(const ulonglong2*)(row + 24);
            ulonglong2 wb3 = *(const ulonglong2*)(row + 28);

            __half2* up = (__half2*)g_uhat + ((size_t)jglob * NN + n) * 16 + dp;

            #pragma unroll
            for (int bb = 0; bb < 8; bb++) {
                int b = bg * 8 + bb;
                const float* xrow = &xs[b * 64 + jl * 16];
                ulonglong2 x0 = *(const ulonglong2*)(xrow);
                ulonglong2 x1 = *(const ulonglong2*)(xrow + 4);
                ulonglong2 x2 = *(const ulonglong2*)(xrow + 8);
                ulonglong2 x3 = *(const ulonglong2*)(xrow + 12);

                unsigned long long a0 = 0ull, a1 = 0ull;
                FMA_F32X2(a0, wa0.x, x0.x, a0);  FMA_F32X2(a1, wb0.x, x0.x, a1);
                FMA_F32X2(a0, wa0.y, x0.y, a0);  FMA_F32X2(a1, wb0.y, x0.y, a1);
                FMA_F32X2(a0, wa1.x, x1.x, a0);  FMA_F32X2(a1, wb1.x, x1.x, a1);
                FMA_F32X2(a0, wa1.y, x1.y, a0);  FMA_F32X2(a1, wb1.y, x1.y, a1);
                FMA_F32X2(a0, wa2.x, x2.x, a0);  FMA_F32X2(a1, wb2.x, x2.x, a1);
                FMA_F32X2(a0, wa2.y, x2.y, a0);  FMA_F32X2(a1, wb2.y, x2.y, a1);
                FMA_F32X2(a0, wa3.x, x3.x, a0);  FMA_F32X2(a1, wb3.x, x3.x, a1);
                FMA_F32X2(a0, wa3.y, x3.y, a0);  FMA_F32X2(a1, wb3.y, x3.y, a1);

                float l0, h0, l1, h1;
                UNPACK_F32X2(l0, h0, a0);
                UNPACK_F32X2(l1, h1, a1);
                float e0 = l0 + h0;
                float e1 = l1 + h1;
                sacc[bb].x += e0;
                sacc[bb].y += e1;
                up[(size_t)b * (JJ * NN * 16)] = __floats2half2_rn(e0, e1);
            }
        }
        __syncthreads();
        buf ^= 1;
    }

    int slice = jc * 2 + js;
    float2* sp2 = (float2*)g_sp;
    #pragma unroll
    for (int bb = 0; bb < 8; bb++)
        sp2[(size_t)slice * (BB * NN * 16) + ((size_t)(bg * 8 + bb) * NN + n) * 16 + dp]
            = sacc[bb];
}

// ---------------- K2: reduce partial slices (MLP=8), squash, write v ----------------
__global__ __launch_bounds__(256) void k2_squash(int nslices, float prescale,
                                                 float* __restrict__ outp) {
    int g = blockIdx.x * 8 + (threadIdx.x >> 5);   // 0..2047 = b*64+n
    int l = threadIdx.x & 31;                      // lane = d
    float a0 = 0.f, a1 = 0.f, a2 = 0.f, a3 = 0.f;
    float a4 = 0.f, a5 = 0.f, a6 = 0.f, a7 = 0.f;
    for (int sl = 0; sl < nslices; sl += 8) {
        size_t base = (size_t)sl * (BB * NN * DD) + (size_t)g * DD + l;
        a0 += g_sp[base + 0ull * (BB * NN * DD)];
        a1 += g_sp[base + 1ull * (BB * NN * DD)];
        a2 += g_sp[base + 2ull * (BB * NN * DD)];
        a3 += g_sp[base + 3ull * (BB * NN * DD)];
        a4 += g_sp[base + 4ull * (BB * NN * DD)];
        a5 += g_sp[base + 5ull * (BB * NN * DD)];
        a6 += g_sp[base + 6ull * (BB * NN * DD)];
        a7 += g_sp[base + 7ull * (BB * NN * DD)];
    }
    float s = (((a0 + a1) + (a2 + a3)) + ((a4 + a5) + (a6 + a7))) * prescale;
    float sq = s * s;
    #pragma unroll
    for (int o = 16; o > 0; o >>= 1) sq += __shfl_xor_sync(0xffffffffu, sq, o);
    float scale = sq / ((1.f + sq) * sqrtf(sq + SQ_EPS));
    float* o = outp ? outp : g_v;
    o[(size_t)g * DD + l] = s * scale;
}

// ---------------- K3: fused routing pass, LDG.64 ownership ----------------
// grid = 32 b * 32 j-groups (64 j), 512 threads, 2 CTAs/SM.
// thread t owns (n = t>>3, dquad = t&7): d = 4dq..4dq+3 via one uint2 load per j.
__global__ __launch_bounds__(512, 2) void k3_route(int first, int last) {
    __shared__ float lg_s[8 * 64];   // logits [j][n]
    __shared__ float c_s[8 * 64];    // coupling [j][n]

    int b  = blockIdx.x >> 5;
    int jg = blockIdx.x & 31;
    int t  = threadIdx.x;
    int n  = t >> 3;      // 0..63
    int w  = t >> 5;      // warp 0..15
    int l  = t & 31;

    // v[b][n][4dq..4dq+3]: float4 index = b*512 + (n*8+dq) = b*512 + t
    float4 vv = ((const float4*)g_v)[b * 512 + t];
    float4 sacc = make_float4(0.f, 0.f, 0.f, 0.f);

    for (int sub = 0; sub < 8; sub++) {
        int j0 = jg * 64 + sub * 8;
        const uint2* ug = (const uint2*)(g_uhat + ((size_t)b * JJ + j0) * (NN * DD));

        // one uint2 (4 halves) per j per thread — 128B/warp fully coalesced
        uint2 ur[8];
        #pragma unroll
        for (int jj = 0; jj < 8; jj++)
            ur[jj] = ug[jj * 512 + t];

        // logits: reduce over the 8-lane dquad group (3 shuffle stages)
        #pragma unroll
        for (int jj = 0; jj < 8; jj++) {
            float2 ua = __half22float2(*(const __half2*)&ur[jj].x);
            float2 ub = __half22float2(*(const __half2*)&ur[jj].y);
            float p = fmaf(ua.x, vv.x, fmaf(ua.y, vv.y,
                      fmaf(ub.x, vv.z, ub.y * vv.w)));
            #pragma unroll
            for (int o = 4; o > 0; o >>= 1)
                p += __shfl_xor_sync(0xffffffffu, p, o);
            if ((t & 7) == 0) lg_s[jj * 64 + n] = p;
        }
        __syncthreads();

        // softmax over n: warp w (w<8) handles j = j0 + w, 2 n per lane
        if (w < 8) {
            float* bl = &g_blog[((size_t)b * JJ + (j0 + w)) * NN];
            float p0 = lg_s[w * 64 + l];
            float p1 = lg_s[w * 64 + 32 + l];
            if (!first) { p0 += bl[l]; p1 += bl[l + 32]; }
            if (!last)  { bl[l] = p0; bl[l + 32] = p1; }
            float m = fmaxf(p0, p1);
            #pragma unroll
            for (int o = 16; o > 0; o >>= 1)
                m = fmaxf(m, __shfl_xor_sync(0xffffffffu, m, o));
            float e0 = __expf(p0 - m), e1 = __expf(p1 - m);
            float ssum = e0 + e1;
            #pragma unroll
            for (int o = 16; o > 0; o >>= 1)
                ssum += __shfl_xor_sync(0xffffffffu, ssum, o);
            float inv = 1.0f / ssum;
            c_s[w * 64 + l]      = e0 * inv;
            c_s[w * 64 + 32 + l] = e1 * inv;
        }
        __syncthreads();

        // s[n][d] += c[j][n] * u[j][n][d] — u still in registers
        #pragma unroll
        for (int jj = 0; jj < 8; jj++) {
            float c = c_s[jj * 64 + n];   // broadcast within 8-lane group
            float2 ua = __half22float2(*(const __half2*)&ur[jj].x);
            float2 ub = __half22float2(*(const __half2*)&ur[jj].y);
            sacc.x = fmaf(c, ua.x, sacc.x);
            sacc.y = fmaf(c, ua.y, sacc.y);
            sacc.z = fmaf(c, ub.x, sacc.z);
            sacc.w = fmaf(c, ub.y, sacc.w);
        }
    }

    // non-atomic partial: slice jg; float4 index = b*512 + (n*8+dq) = b*512 + t
    ((float4*)g_sp)[(size_t)jg * (BB * NN * DD / 4) + (size_t)b * 512 + t] = sacc;
}

// ---------------- launch ----------------
extern "C" void kernel_launch(void* const* d_in, const int* in_sizes, int n_in,
                              void* d_out, int out_size) {
    const float* x = (const float*)d_in[0];
    const float* W = (const float*)d_in[1];
    if (n_in >= 2 && in_sizes[0] != BB * JJ * II) {
        x = (const float*)d_in[1];
        W = (const float*)d_in[0];
    }
    float* out = (float*)d_out;

    cudaFuncSetAttribute(k1_uhat, cudaFuncAttributeMaxDynamicSharedMemorySize, K1_SMEM);

    k1_uhat<<<1024, 256, K1_SMEM>>>(x, W);             // u_hat + 64 s-partial slices
    k2_squash<<<256, 256>>>(64, 1.0f / NN, nullptr);   // v0
    k3_route<<<1024, 512>>>(1, 0);                     // b1, c1, s1 partials
    k2_squash<<<256, 256>>>(32, 1.0f, nullptr);        // v1
    k3_route<<<1024, 512>>>(0, 1);                     // b2, c2, s2 partials
    k2_squash<<<256, 256>>>(32, 1.0f, out);            // v2 -> output
}

// round 16
// speedup vs baseline: 1.2292x; 1.2292x over previous
#include <cuda_runtime.h>
#include <cuda_fp16.h>
#include <cstdint>

#define BB 32
#define JJ 2048
#define II 16
#define NN 64
#define DD 32
#define SQ_EPS 1e-7f

// ---------------- device scratch (no allocations allowed) ----------------
// u_hat layout: [j][n][b][d]  (fp16) — 268 MB
__device__ __half g_uhat[(size_t)JJ * NN * BB * DD];
__device__ float  g_v[BB * NN * DD];                   // [b][n][d]
__device__ float  g_blog[(size_t)BB * JJ * NN];        // [b][j][n], 16 MB
__device__ float  g_sp[64 * BB * NN * DD];             // partial s slices [slice][b][n][d]

// ---------------- helpers ----------------
__device__ __forceinline__ uint32_t f16x2(float hi, float lo) {
    uint32_t r;
    asm("cvt.rn.f16x2.f32 %0, %1, %2;" : "=r"(r) : "f"(hi), "f"(lo));
    return r;
}
__device__ __forceinline__ void mma16816(float d[4], const uint32_t a[4],
                                         const uint32_t b[2], const float c[4]) {
    asm volatile("mma.sync.aligned.m16n8k16.row.col.f32.f16.f16.f32 "
        "{%0,%1,%2,%3}, {%4,%5,%6,%7}, {%8,%9}, {%10,%11,%12,%13};"
        : "=f"(d[0]), "=f"(d[1]), "=f"(d[2]), "=f"(d[3])
        : "r"(a[0]), "r"(a[1]), "r"(a[2]), "r"(a[3]),
          "r"(b[0]), "r"(b[1]),
          "f"(c[0]), "f"(c[1]), "f"(c[2]), "f"(c[3]));
}

// ---------------- K1 (HMMA): u_hat + register s-partials ----------------
// grid = 8 n-octets * 64 j-chunks (32 j each), 256 thr (8 warps).
// Warp owns n = no*8+w, loops 32 j: per j, D[32d x 32b] = W[n,j] @ x_j^T
// via 2x4 mma.m16n8k16; Dacc (32 regs) accumulates sum_j; per-warp smem
// transpose (pad 36, conflict-free) -> coalesced fp16 stores.
#define TP 36

__global__ __launch_bounds__(256, 2) void k1_hmma(const float* __restrict__ x,
                                                  const float* __restrict__ W) {
    __shared__ __align__(16) float T[8][32 * TP];
    int no = blockIdx.x >> 6;      // n-octet 0..7
    int jc = blockIdx.x & 63;      // j-chunk 0..63 (32 j each)
    int t = threadIdx.x, w = t >> 5, lane = t & 31;
    int g = lane >> 2, tg = lane & 3;
    int n = no * 8 + w;
    float* Tw = T[w];

    float dacc[8][4];
    #pragma unroll
    for (int i = 0; i < 8; i++)
        #pragma unroll
        for (int k = 0; k < 4; k++) dacc[i][k] = 0.f;
    const float zero4[4] = {0.f, 0.f, 0.f, 0.f};

    #pragma unroll 2
    for (int jj = 0; jj < 32; jj++) {
        int j = jc * 32 + jj;

        // B fragments (x_j, 32b x 16i, L2-resident): b = 8ni + g, k = 2tg(+1), +8
        uint32_t bfr[4][2];
        #pragma unroll
        for (int ni = 0; ni < 4; ni++) {
            const float* xb = x + ((size_t)(8 * ni + g) * JJ + j) * II + 2 * tg;
            float2 v0 = *(const float2*)(xb);
            float2 v1 = *(const float2*)(xb + 8);
            bfr[ni][0] = f16x2(v0.y, v0.x);
            bfr[ni][1] = f16x2(v1.y, v1.x);
        }

        const float* Wb = W + (((size_t)n * JJ + j) << 9);   // W[n][j][32d][16i]
        #pragma unroll
        for (int mi = 0; mi < 2; mi++) {
            // A fragment rows: d = 16mi + g (+8), k = 2tg (+8)
            const float* Wt = Wb + mi * 256 + 2 * tg;
            float2 v0 = *(const float2*)(Wt + g * 16);
            float2 v1 = *(const float2*)(Wt + (g + 8) * 16);
            float2 v2 = *(const float2*)(Wt + g * 16 + 8);
            float2 v3 = *(const float2*)(Wt + (g + 8) * 16 + 8);
            uint32_t afr[4] = { f16x2(v0.y, v0.x), f16x2(v1.y, v1.x),
                                f16x2(v2.y, v2.x), f16x2(v3.y, v3.x) };
            #pragma unroll
            for (int ni = 0; ni < 4; ni++) {
                float dj[4];
                mma16816(dj, afr, bfr[ni], zero4);
                #pragma unroll
                for (int k = 0; k < 4; k++) dacc[mi * 4 + ni][k] += dj[k];
                // D cell (d = 16mi+g(+8), b = 8ni+2tg(+1)) -> T[b][d] pad-36
                int b0 = 8 * ni + 2 * tg, d0 = 16 * mi + g;
                Tw[b0 * TP + d0]           = dj[0];
                Tw[(b0 + 1) * TP + d0]     = dj[1];
                Tw[b0 * TP + d0 + 8]       = dj[2];
                Tw[(b0 + 1) * TP + d0 + 8] = dj[3];
            }
        }
        __syncwarp();

        // epilogue: lane = b reads its d-row, packs fp16, coalesced 64B store
        uint4* up = (uint4*)g_uhat + (((size_t)j * NN + n) * BB + lane) * 4;
        #pragma unroll
        for (int q = 0; q < 4; q++) {
            float4 fa = *(const float4*)&Tw[lane * TP + q * 8];
            float4 fb = *(const float4*)&Tw[lane * TP + q * 8 + 4];
            up[q] = make_uint4(f16x2(fa.y, fa.x), f16x2(fa.w, fa.z),
                               f16x2(fb.y, fb.x), f16x2(fb.w, fb.z));
        }
        __syncwarp();   // Tw free before next iteration's STS
    }

    // flush Dacc (sum over this warp's 32 j) through the same transpose
    #pragma unroll
    for (int mi = 0; mi < 2; mi++)
        #pragma unroll
        for (int ni = 0; ni < 4; ni++) {
            int b0 = 8 * ni + 2 * tg, d0 = 16 * mi + g;
            Tw[b0 * TP + d0]           = dacc[mi * 4 + ni][0];
            Tw[(b0 + 1) * TP + d0]     = dacc[mi * 4 + ni][1];
            Tw[b0 * TP + d0 + 8]       = dacc[mi * 4 + ni][2];
            Tw[(b0 + 1) * TP + d0 + 8] = dacc[mi * 4 + ni][3];
        }
    __syncwarp();
    // slice = jc (64 slices); g_sp[slice][b][n][d], lane = b, 128 B contiguous
    float* sp = g_sp + (((size_t)jc * BB + lane) * NN + n) * DD;
    #pragma unroll
    for (int q = 0; q < 8; q++)
        *(float4*)(sp + q * 4) = *(const float4*)&Tw[lane * TP + q * 4];
}

// ---------------- K2: reduce partial slices (MLP=4, R13-proven), squash ----------------
__global__ __launch_bounds__(256) void k2_squash(int nslices, float prescale,
                                                 float* __restrict__ outp) {
    int g = blockIdx.x * 8 + (threadIdx.x >> 5);   // 0..2047 = b*64+n
    int l = threadIdx.x & 31;                      // lane = d
    float s0 = 0.f, s1 = 0.f, s2 = 0.f, s3 = 0.f;
    for (int sl = 0; sl < nslices; sl += 4) {
        s0 += g_sp[(size_t)(sl + 0) * (BB * NN * DD) + (size_t)g * DD + l];
        s1 += g_sp[(size_t)(sl + 1) * (BB * NN * DD) + (size_t)g * DD + l];
        s2 += g_sp[(size_t)(sl + 2) * (BB * NN * DD) + (size_t)g * DD + l];
        s3 += g_sp[(size_t)(sl + 3) * (BB * NN * DD) + (size_t)g * DD + l];
    }
    float s = ((s0 + s1) + (s2 + s3)) * prescale;
    float sq = s * s;
    #pragma unroll
    for (int o = 16; o > 0; o >>= 1) sq += __shfl_xor_sync(0xffffffffu, sq, o);
    float scale = sq / ((1.f + sq) * sqrtf(sq + SQ_EPS));
    float* o = outp ? outp : g_v;
    o[(size_t)g * DD + l] = s * scale;
}

// ---------------- K3: fused routing (R13-proven structure, reindexed) ----------------
// u_hat layout [j][n][b][d]; thread t owns (n0 = t>>4, dp = t&15) and (n0+32, dp).
__global__ __launch_bounds__(512, 2) void k3_route(int first, int last) {
    __shared__ float lg_s[8 * 64];
    __shared__ float c_s[8 * 64];

    int b  = blockIdx.x >> 5;
    int jg = blockIdx.x & 31;
    int t  = threadIdx.x;
    int n0 = t >> 4;
    int w  = t >> 5;
    int l  = t & 31;
    int dp = t & 15;

    float2 vv0 = ((const float2*)g_v)[b * 1024 + t];
    float2 vv1 = ((const float2*)g_v)[b * 1024 + 512 + t];
    float2 sacc0 = make_float2(0.f, 0.f);
    float2 sacc1 = make_float2(0.f, 0.f);

    // half2 index (j,n,b,dp) = j*32768 + n*512 + b*16 + dp
    const unsigned* ug = (const unsigned*)g_uhat;
    size_t off0 = (size_t)b * 16 + (size_t)n0 * 512 + dp;
    size_t off1 = off0 + 32ull * 512;

    for (int sub = 0; sub < 8; sub++) {
        int j0 = jg * 64 + sub * 8;
        const unsigned* ugj = ug + (size_t)j0 * 32768;

        unsigned ur0[8], ur1[8];
        #pragma unroll
        for (int jj = 0; jj < 8; jj++) {
            ur0[jj] = ugj[(size_t)jj * 32768 + off0];
            ur1[jj] = ugj[(size_t)jj * 32768 + off1];
        }

        #pragma unroll
        for (int jj = 0; jj < 8; jj++) {
            float2 uf0 = __half22float2(*(const __half2*)&ur0[jj]);
            float2 uf1 = __half22float2(*(const __half2*)&ur1[jj]);
            float p0 = fmaf(uf0.x, vv0.x, uf0.y * vv0.y);
            float p1 = fmaf(uf1.x, vv1.x, uf1.y * vv1.y);
            #pragma unroll
            for (int o = 8; o > 0; o >>= 1) {
                p0 += __shfl_xor_sync(0xffffffffu, p0, o);
                p1 += __shfl_xor_sync(0xffffffffu, p1, o);
            }
            if ((t & 15) == 0) {
                lg_s[jj * 64 + n0]      = p0;
                lg_s[jj * 64 + n0 + 32] = p1;
            }
        }
        __syncthreads();

        if (w < 8) {
            float* bl = &g_blog[((size_t)b * JJ + (j0 + w)) * NN];
            float p0 = lg_s[w * 64 + l];
            float p1 = lg_s[w * 64 + 32 + l];
            if (!first) { p0 += bl[l]; p1 += bl[l + 32]; }
            if (!last)  { bl[l] = p0; bl[l + 32] = p1; }
            float m = fmaxf(p0, p1);
            #pragma unroll
            for (int o = 16; o > 0; o >>= 1)
                m = fmaxf(m, __shfl_xor_sync(0xffffffffu, m, o));
            float e0 = __expf(p0 - m), e1 = __expf(p1 - m);
            float ssum = e0 + e1;
            #pragma unroll
            for (int o = 16; o > 0; o >>= 1)
                ssum += __shfl_xor_sync(0xffffffffu, ssum, o);
            float inv = 1.0f / ssum;
            c_s[w * 64 + l]      = e0 * inv;
            c_s[w * 64 + 32 + l] = e1 * inv;
        }
        __syncthreads();

        #pragma unroll
        for (int jj = 0; jj < 8; jj++) {
            float c0 = c_s[jj * 64 + n0];
            float c1 = c_s[jj * 64 + n0 + 32];
            float2 uf0 = __half22float2(*(const __half2*)&ur0[jj]);
            float2 uf1 = __half22float2(*(const __half2*)&ur1[jj]);
            sacc0.x = fmaf(c0, uf0.x, sacc0.x);
            sacc0.y = fmaf(c0, uf0.y, sacc0.y);
            sacc1.x = fmaf(c1, uf1.x, sacc1.x);
            sacc1.y = fmaf(c1, uf1.y, sacc1.y);
        }
    }

    float2* sp = (float2*)g_sp;
    sp[(size_t)jg * (BB * NN * DD / 2) + (size_t)b * 1024 + t]       = sacc0;
    sp[(size_t)jg * (BB * NN * DD / 2) + (size_t)b * 1024 + 512 + t] = sacc1;
}

// ---------------- launch ----------------
extern "C" void kernel_launch(void* const* d_in, const int* in_sizes, int n_in,
                              void* d_out, int out_size) {
    const float* x = (const float*)d_in[0];
    const float* W = (const float*)d_in[1];
    if (n_in >= 2 && in_sizes[0] != BB * JJ * II) {
        x = (const float*)d_in[1];
        W = (const float*)d_in[0];
    }
    float* out = (float*)d_out;

    k1_hmma<<<512, 256>>>(x, W);                       // u_hat (fp16) + 64 s-partial slices
    k2_squash<<<256, 256>>>(64, 1.0f / NN, nullptr);   // v0 = squash(sum/64)
    k3_route<<<1024, 512>>>(1, 0);                     // b1, c1, s1 partials
    k2_squash<<<256, 256>>>(32, 1.0f, nullptr);        // v1
    k3_route<<<1024, 512>>>(0, 1);                     // b2, c2, s2 partials
    k2_squash<<<256, 256>>>(32, 1.0f, out);            // v2 -> output
}

// round 17
// speedup vs baseline: 1.3545x; 1.1019x over previous
#include <cuda_runtime.h>
#include <cuda_fp16.h>
#include <cstdint>

#define BB 32
#define JJ 2048
#define II 16
#define NN 64
#define DD 32
#define SQ_EPS 1e-7f

// ---------------- device scratch (no allocations allowed) ----------------
// u_hat layout: [b][j][n][d] (fp16) — 268 MB  (k3-friendly, R13-proven)
__device__ __half g_uhat[(size_t)BB * JJ * NN * DD];
__device__ float  g_v[BB * NN * DD];                   // v0 (then stays v0)
__device__ float  g_vsum[BB * NN * DD];                // v0 + v1
__device__ float  g_sp[64 * BB * NN * DD];             // partial s slices [slice][b][n][d]

// ---------------- helpers ----------------
__device__ __forceinline__ uint32_t f16x2(float hi, float lo) {
    uint32_t r;
    asm("cvt.rn.f16x2.f32 %0, %1, %2;" : "=r"(r) : "f"(hi), "f"(lo));
    return r;
}
__device__ __forceinline__ void mma16816(float d[4], const uint32_t a[4],
                                         const uint32_t b[2], const float c[4]) {
    asm volatile("mma.sync.aligned.m16n8k16.row.col.f32.f16.f16.f32 "
        "{%0,%1,%2,%3}, {%4,%5,%6,%7}, {%8,%9}, {%10,%11,%12,%13};"
        : "=f"(d[0]), "=f"(d[1]), "=f"(d[2]), "=f"(d[3])
        : "r"(a[0]), "r"(a[1]), "r"(a[2]), "r"(a[3]),
          "r"(b[0]), "r"(b[1]),
          "f"(c[0]), "f"(c[1]), "f"(c[2]), "f"(c[3]));
}

// ---------------- K1 (HMMA): u_hat + register s-partials ----------------
// grid = 8 n-octets * 64 j-chunks (32 j each), 256 thr (8 warps).
// Warp w owns n = no*8+w; per j: D[32d x 32b] = W[n,j] @ x_j^T via 2x4 m16n8k16.
// Per-warp transpose tile T[w] ([b][d], pad 36), then BLOCK-cooperative store
// reassembles [32b][8n][32d] into u_hat's [b][j][n][d] layout, fully coalesced.
#define TP 36

__global__ __launch_bounds__(256, 2) void k1_hmma(const float* __restrict__ x,
                                                  const float* __restrict__ W) {
    __shared__ __align__(16) float T[8][32 * TP];
    int no = blockIdx.x >> 6;      // n-octet 0..7
    int jc = blockIdx.x & 63;      // j-chunk 0..63 (32 j each)
    int t = threadIdx.x, w = t >> 5, lane = t & 31;
    int g = lane >> 2, tg = lane & 3;
    int n = no * 8 + w;
    float* Tw = T[w];

    float dacc[8][4];
    #pragma unroll
    for (int i = 0; i < 8; i++)
        #pragma unroll
        for (int k = 0; k < 4; k++) dacc[i][k] = 0.f;
    const float zero4[4] = {0.f, 0.f, 0.f, 0.f};

    for (int jj = 0; jj < 32; jj++) {
        int j = jc * 32 + jj;

        // B fragments (x_j, 32b x 16i, L2-resident): b = 8ni + g, k = 2tg(+1), +8
        uint32_t bfr[4][2];
        #pragma unroll
        for (int ni = 0; ni < 4; ni++) {
            const float* xb = x + ((size_t)(8 * ni + g) * JJ + j) * II + 2 * tg;
            float2 v0 = *(const float2*)(xb);
            float2 v1 = *(const float2*)(xb + 8);
            bfr[ni][0] = f16x2(v0.y, v0.x);
            bfr[ni][1] = f16x2(v1.y, v1.x);
        }

        const float* Wb = W + (((size_t)n * JJ + j) << 9);   // W[n][j][32d][16i]
        #pragma unroll
        for (int mi = 0; mi < 2; mi++) {
            const float* Wt = Wb + mi * 256 + 2 * tg;
            float2 v0 = *(const float2*)(Wt + g * 16);
            float2 v1 = *(const float2*)(Wt + (g + 8) * 16);
            float2 v2 = *(const float2*)(Wt + g * 16 + 8);
            float2 v3 = *(const float2*)(Wt + (g + 8) * 16 + 8);
            uint32_t afr[4] = { f16x2(v0.y, v0.x), f16x2(v1.y, v1.x),
                                f16x2(v2.y, v2.x), f16x2(v3.y, v3.x) };
            #pragma unroll
            for (int ni = 0; ni < 4; ni++) {
                float dj[4];
                mma16816(dj, afr, bfr[ni], zero4);
                #pragma unroll
                for (int k = 0; k < 4; k++) dacc[mi * 4 + ni][k] += dj[k];
                int b0 = 8 * ni + 2 * tg, d0 = 16 * mi + g;
                Tw[b0 * TP + d0]           = dj[0];
                Tw[(b0 + 1) * TP + d0]     = dj[1];
                Tw[b0 * TP + d0 + 8]       = dj[2];
                Tw[(b0 + 1) * TP + d0 + 8] = dj[3];
            }
        }
        __syncthreads();   // all warps' T tiles complete for this j

        // block-cooperative store: 4 rounds, each warp covers 512B contiguous.
        // unit (16B) = b*32 + nn*4 + q; LDS = broadcast x8 over 4 addrs (CF).
        #pragma unroll
        for (int k = 0; k < 4; k++) {
            int unit = k * 256 + t;
            int q  = unit & 3;
            int nn = (unit >> 2) & 7;
            int bb = unit >> 5;
            const float* src = &T[nn][bb * TP + q * 8];
            float4 fa = *(const float4*)(src);
            float4 fb = *(const float4*)(src + 4);
            uint4 val = make_uint4(f16x2(fa.y, fa.x), f16x2(fa.w, fa.z),
                                   f16x2(fb.y, fb.x), f16x2(fb.w, fb.z));
            ((uint4*)g_uhat)[(((size_t)bb * JJ + j) * NN + no * 8 + nn) * 4 + q] = val;
        }
        __syncthreads();   // stores done before next j overwrites T
    }

    // flush Dacc (sum over this warp's 32 j) through the per-warp transpose
    #pragma unroll
    for (int mi = 0; mi < 2; mi++)
        #pragma unroll
        for (int ni = 0; ni < 4; ni++) {
            int b0 = 8 * ni + 2 * tg, d0 = 16 * mi + g;
            Tw[b0 * TP + d0]           = dacc[mi * 4 + ni][0];
            Tw[(b0 + 1) * TP + d0]     = dacc[mi * 4 + ni][1];
            Tw[b0 * TP + d0 + 8]       = dacc[mi * 4 + ni][2];
            Tw[(b0 + 1) * TP + d0 + 8] = dacc[mi * 4 + ni][3];
        }
    __syncwarp();
    // slice = jc (64 slices); g_sp[slice][b][n][d], lane = b, 128B contiguous
    float* sp = g_sp + (((size_t)jc * BB + lane) * NN + n) * DD;
    #pragma unroll
    for (int q = 0; q < 8; q++)
        *(float4*)(sp + q * 4) = *(const float4*)&Tw[lane * TP + q * 4];
}

// ---------------- K2: reduce slices, squash; mode 0: g_v, 1: g_vsum+=, 2: outp ----------------
__global__ __launch_bounds__(256) void k2_squash(int nslices, float prescale,
                                                 float* __restrict__ outp, int mode) {
    int g = blockIdx.x * 8 + (threadIdx.x >> 5);   // 0..2047 = b*64+n
    int l = threadIdx.x & 31;                      // lane = d
    float s0 = 0.f, s1 = 0.f, s2 = 0.f, s3 = 0.f;
    for (int sl = 0; sl < nslices; sl += 4) {
        s0 += g_sp[(size_t)(sl + 0) * (BB * NN * DD) + (size_t)g * DD + l];
        s1 += g_sp[(size_t)(sl + 1) * (BB * NN * DD) + (size_t)g * DD + l];
        s2 += g_sp[(size_t)(sl + 2) * (BB * NN * DD) + (size_t)g * DD + l];
        s3 += g_sp[(size_t)(sl + 3) * (BB * NN * DD) + (size_t)g * DD + l];
    }
    float s = ((s0 + s1) + (s2 + s3)) * prescale;
    float sq = s * s;
    #pragma unroll
    for (int o = 16; o > 0; o >>= 1) sq += __shfl_xor_sync(0xffffffffu, sq, o);
    float scale = sq / ((1.f + sq) * sqrtf(sq + SQ_EPS));
    float vnew = s * scale;
    if (mode == 0)      g_v[(size_t)g * DD + l] = vnew;
    else if (mode == 1) g_vsum[(size_t)g * DD + l] = g_v[(size_t)g * DD + l] + vnew;
    else                outp[(size_t)g * DD + l] = vnew;
}

// ---------------- K3: fused routing (R13-exact structure; blog eliminated) ----------------
// logits are linear in v: pass 1 uses v0, pass 2 uses v0+v1 -> no logit carry.
__global__ __launch_bounds__(512, 2) void k3_route(int useVsum) {
    __shared__ float lg_s[8 * 64];
    __shared__ float c_s[8 * 64];

    int b  = blockIdx.x >> 5;
    int jg = blockIdx.x & 31;
    int t  = threadIdx.x;
    int n0 = t >> 4;
    int w  = t >> 5;
    int l  = t & 31;

    const float* vp = useVsum ? g_vsum : g_v;
    float2 vv0 = ((const float2*)vp)[b * 1024 + t];
    float2 vv1 = ((const float2*)vp)[b * 1024 + 512 + t];
    float2 sacc0 = make_float2(0.f, 0.f);
    float2 sacc1 = make_float2(0.f, 0.f);

    for (int sub = 0; sub < 8; sub++) {
        int j0 = jg * 64 + sub * 8;
        const unsigned* ug = (const unsigned*)(g_uhat + ((size_t)b * JJ + j0) * (NN * DD));

        unsigned ur0[8], ur1[8];
        #pragma unroll
        for (int jj = 0; jj < 8; jj++) {
            ur0[jj] = ug[jj * 1024 + t];
            ur1[jj] = ug[jj * 1024 + 512 + t];
        }

        #pragma unroll
        for (int jj = 0; jj < 8; jj++) {
            float2 uf0 = __half22float2(*(const __half2*)&ur0[jj]);
            float2 uf1 = __half22float2(*(const __half2*)&ur1[jj]);
            float p0 = fmaf(uf0.x, vv0.x, uf0.y * vv0.y);
            float p1 = fmaf(uf1.x, vv1.x, uf1.y * vv1.y);
            #pragma unroll
            for (int o = 8; o > 0; o >>= 1) {
                p0 += __shfl_xor_sync(0xffffffffu, p0, o);
                p1 += __shfl_xor_sync(0xffffffffu, p1, o);
            }
            if ((t & 15) == 0) {
                lg_s[jj * 64 + n0]      = p0;
                lg_s[jj * 64 + n0 + 32] = p1;
            }
        }
        __syncthreads();

        if (w < 8) {
            float p0 = lg_s[w * 64 + l];
            float p1 = lg_s[w * 64 + 32 + l];
            float m = fmaxf(p0, p1);
            #pragma unroll
            for (int o = 16; o > 0; o >>= 1)
                m = fmaxf(m, __shfl_xor_sync(0xffffffffu, m, o));
            float e0 = __expf(p0 - m), e1 = __expf(p1 - m);
            float ssum = e0 + e1;
            #pragma unroll
            for (int o = 16; o > 0; o >>= 1)
                ssum += __shfl_xor_sync(0xffffffffu, ssum, o);
            float inv = 1.0f / ssum;
            c_s[w * 64 + l]      = e0 * inv;
            c_s[w * 64 + 32 + l] = e1 * inv;
        }
        __syncthreads();

        #pragma unroll
        for (int jj = 0; jj < 8; jj++) {
            float c0 = c_s[jj * 64 + n0];
            float c1 = c_s[jj * 64 + n0 + 32];
            float2 uf0 = __half22float2(*(const __half2*)&ur0[jj]);
            float2 uf1 = __half22float2(*(const __half2*)&ur1[jj]);
            sacc0.x = fmaf(c0, uf0.x, sacc0.x);
            sacc0.y = fmaf(c0, uf0.y, sacc0.y);
            sacc1.x = fmaf(c1, uf1.x, sacc1.x);
            sacc1.y = fmaf(c1, uf1.y, sacc1.y);
        }
    }

    float2* sp = (float2*)g_sp;
    sp[(size_t)jg * (BB * NN * DD / 2) + (size_t)b * 1024 + t]       = sacc0;
    sp[(size_t)jg * (BB * NN * DD / 2) + (size_t)b * 1024 + 512 + t] = sacc1;
}

// ---------------- launch ----------------
extern "C" void kernel_launch(void* const* d_in, const int* in_sizes, int n_in,
                              void* d_out, int out_size) {
    const float* x = (const float*)d_in[0];
    const float* W = (const float*)d_in[1];
    if (n_in >= 2 && in_sizes[0] != BB * JJ * II) {
        x = (const float*)d_in[1];
        W = (const float*)d_in[0];
    }
    float* out = (float*)d_out;

    k1_hmma<<<512, 256>>>(x, W);                            // u_hat + 64 s-partial slices
    k2_squash<<<256, 256>>>(64, 1.0f / NN, nullptr, 0);     // v0 -> g_v
    k3_route<<<1024, 512>>>(0);                             // c1 = softmax(v0·u), s1
    k2_squash<<<256, 256>>>(32, 1.0f, nullptr, 1);          // v1; g_vsum = v0+v1
    k3_route<<<1024, 512>>>(1);                             // c2 = softmax((v0+v1)·u), s2
    k2_squash<<<256, 256>>>(32, 1.0f, out, 2);              // v2 -> output
}